// round 17
// baseline (speedup 1.0000x reference)
#include <cuda_runtime.h>
#include <cstdint>

#define NS 25
#define NC 80
#define CD 6400
#define BT 25600

#define MTB 128
#define NTB 128
#define THREADS 256
#define MTILES 200

#define NBLK 444             // 3 * 148: exactly one wave at 3 blocks/SM
#define NU_C 10000           // 50 stripes * 200 m-tiles
#define NU_M 200
#define NU_T (NU_C + NU_M)

#define PL 16
#define PSTR 132             // uint2 per A plane
#define PSTRB 136            // uint32 per B plane (== 8 mod 32)

// dynamic smem layout (bytes)
#define OFF_AHL 0                              // 16*132*8 = 16896
#define OFF_BH  16896                          // 16*136*4 = 8704
#define OFF_BL  25600                          // 8704
#define OFF_SC  34304                          // 13 float2
#define OFF_SCS 34432                          // 25 floats (+pad)
#define SMB     34560
// m-path buffers alias the A region (only used after all C units)
#define OFF_MUS OFF_AHL                        // 2048 floats
#define OFF_AS  (OFF_AHL + 8192)               // 3232 floats (ends 21120 < 23968)

__device__ __forceinline__ uint16_t f2bf(float v) {
    uint16_t r;
    asm("cvt.rn.bf16.f32 %0, %1;" : "=h"(r) : "f"(v));
    return r;
}
__device__ __forceinline__ float bf2f(uint16_t h) {
    return __uint_as_float((uint32_t)h << 16);
}
__device__ __forceinline__ void mma_bf16(float* acc, const uint32_t* a,
                                         uint32_t b0, uint32_t b1) {
    asm volatile(
        "mma.sync.aligned.m16n8k16.row.col.f32.bf16.bf16.f32 "
        "{%0,%1,%2,%3}, {%4,%5,%6,%7}, {%8,%9}, {%0,%1,%2,%3};"
        : "+f"(acc[0]), "+f"(acc[1]), "+f"(acc[2]), "+f"(acc[3])
        : "r"(a[0]), "r"(a[1]), "r"(a[2]), "r"(a[3]), "r"(b0), "r"(b1));
}
__device__ __forceinline__ int pidx(int plane, int x) {
    return plane * PSTR + (x ^ ((plane & 3) << 3));
}
// B permutation: col c (0..15 in-block) = 4Q + q + 2s  ->  8s + 2Q + q
__device__ __forceinline__ int bperm(int n) {
    const int c = n & 15;
    return (n & ~15) + (((c & 2) << 2) | ((c >> 2) << 1) | (c & 1));
}
__device__ __forceinline__ float softplus_f(float x) { return log1pf(expf(x)); }

// ---------------------------------------------------------------------------
__global__ __launch_bounds__(THREADS, 3)
void fused_kernel(const float* __restrict__ alpha,
                  const float* __restrict__ mu,
                  const float* __restrict__ D,
                  const float* __restrict__ asc,
                  float* __restrict__ m_out,
                  float* __restrict__ C)
{
    extern __shared__ char dsm[];
    uint2*    AHL  = reinterpret_cast<uint2*>(dsm + OFF_AHL);
    uint32_t* BH   = reinterpret_cast<uint32_t*>(dsm + OFF_BH);
    uint32_t* BL   = reinterpret_cast<uint32_t*>(dsm + OFF_BL);
    float2*   sc2  = reinterpret_cast<float2*>(dsm + OFF_SC);
    float*    scs  = reinterpret_cast<float*>(dsm + OFF_SCS);
    float*    mu_s = reinterpret_cast<float*>(dsm + OFF_MUS);
    float*    a_s  = reinterpret_cast<float*>(dsm + OFF_AS);

    const int tid = threadIdx.x;
    const int bid = blockIdx.x;

    // one-time init (covered by the first per-unit __syncthreads)
    if (tid < NS) scs[tid] = softplus_f(asc[tid]);
    if (tid >= 32 && tid < 32 + 13) {
        const int t = tid - 32;
        const float s0 = softplus_f(asc[2 * t]);
        const float s1 = (t < 12) ? softplus_f(asc[2 * t + 1]) : 0.f;
        sc2[t] = make_float2(s0, s1);
    }
    for (int i = tid; i < 3 * PSTR; i += THREADS)
        AHL[13 * PSTR + i] = make_uint2(0, 0);
    for (int i = tid; i < 3 * PSTRB; i += THREADS) {
        BH[13 * PSTRB + i] = 0;
        BL[13 * PSTRB + i] = 0;
    }

    const int u0 = (int)((long long)bid * NU_T / NBLK);
    const int u1 = (int)((long long)(bid + 1) * NU_T / NBLK);

    const int w = tid >> 5, lane = tid & 31;
    const int grp = lane >> 2, kk = lane & 3;
    const int rowg = w >> 1;
    const int sh   = w & 1;
    const int kkx  = kk << 3;
    const int cb0  = sh * 64 + grp;
    const int mc = tid % 80, mh = tid / 80;       // m-path mapping
    const bool mact = (tid < 160);

    int cur_stripe = -1;

    for (int u = u0; u < u1; u++) {
        if (u < NU_C) {
            // =================== C unit ===================
            const int stripe = u / MTILES;
            const int mt = u - stripe * MTILES;
            const int nb = stripe * NTB;
            const int m0 = mt * MTB;

            __syncthreads();
            if (stripe != cur_stripe) {
                // B split: permuted uint32 hi/lo planes
                for (int it = tid; it < 13 * NTB; it += THREADS) {
                    const int kp = it >> 7, n = it & 127;
                    const float v0 = D[(size_t)(2 * kp) * CD + nb + n];
                    const float v1 = (kp < 12) ? D[(size_t)(2 * kp + 1) * CD + nb + n] : 0.f;
                    const uint16_t h0 = f2bf(v0), h1 = f2bf(v1);
                    const uint16_t l0 = f2bf(v0 - bf2f(h0)), l1 = f2bf(v1 - bf2f(h1));
                    const int idx = kp * PSTRB + bperm(n);
                    BH[idx] = (uint32_t)h0 | ((uint32_t)h1 << 16);
                    BL[idx] = (uint32_t)l0 | ((uint32_t)l1 << 16);
                }
                cur_stripe = stripe;
            }
            // A split: pair-granular
            {
                const float* ap = alpha + (size_t)m0 * NS;
                for (int i = tid; i < MTB * 13; i += THREADS) {
                    const int r = i / 13, kp = i - r * 13;
                    const float2 s = sc2[kp];
                    const float v0 = ap[r * NS + 2 * kp] * s.x;
                    const float v1 = (kp < 12) ? ap[r * NS + 2 * kp + 1] * s.y : 0.f;
                    const uint16_t h0 = f2bf(v0), h1 = f2bf(v1);
                    const uint16_t l0 = f2bf(v0 - bf2f(h0)), l1 = f2bf(v1 - bf2f(h1));
                    AHL[pidx(kp, r)] = make_uint2((uint32_t)h0 | ((uint32_t)h1 << 16),
                                                  (uint32_t)l0 | ((uint32_t)l1 << 16));
                }
            }
            __syncthreads();

            // a-fragments (hi+lo), register-resident
            uint32_t ah[2][2][4], al[2][2][4];
            #pragma unroll
            for (int m = 0; m < 2; m++) {
                const int rb = rowg * 32 + m * 16 + grp;
                #pragma unroll
                for (int g = 0; g < 2; g++) {
                    const int p0 = g * 8 + kk;
                    uint2 t;
                    t = AHL[p0 * PSTR + ((rb)     ^ kkx)]; ah[m][g][0] = t.x; al[m][g][0] = t.y;
                    t = AHL[p0 * PSTR + ((rb + 8) ^ kkx)]; ah[m][g][1] = t.x; al[m][g][1] = t.y;
                    t = AHL[(p0 + 4) * PSTR + ((rb)     ^ kkx)]; ah[m][g][2] = t.x; al[m][g][2] = t.y;
                    t = AHL[(p0 + 4) * PSTR + ((rb + 8) ^ kkx)]; ah[m][g][3] = t.x; al[m][g][3] = t.y;
                }
            }

            float* Cw = C + (size_t)(m0 + rowg * 32) * CD + nb + sh * 64 + kk * 4;

            #pragma unroll
            for (int p = 0; p < 4; p++) {
                float acc[2][2][4];
                #pragma unroll
                for (int v = 0; v < 2; v++)
                    #pragma unroll
                    for (int m = 0; m < 2; m++)
                        #pragma unroll
                        for (int q = 0; q < 4; q++) acc[v][m][q] = 0.f;

                const int cb = cb0 + p * 16;
                #pragma unroll
                for (int g = 0; g < 2; g++) {
                    const int pA = (g * 8 + kk) * PSTRB + cb;
                    const int pB = pA + 4 * PSTRB;
                    const uint32_t bhA0 = BH[pA],     bhA1 = BH[pB];
                    const uint32_t blA0 = BL[pA],     blA1 = BL[pB];
                    const uint32_t bhB0 = BH[pA + 8], bhB1 = BH[pB + 8];
                    const uint32_t blB0 = BL[pA + 8], blB1 = BL[pB + 8];
                    #pragma unroll
                    for (int m = 0; m < 2; m++) {
                        mma_bf16(acc[0][m], ah[m][g], bhA0, bhA1);
                        mma_bf16(acc[0][m], al[m][g], bhA0, bhA1);
                        mma_bf16(acc[0][m], ah[m][g], blA0, blA1);
                        mma_bf16(acc[1][m], ah[m][g], bhB0, bhB1);
                        mma_bf16(acc[1][m], al[m][g], bhB0, bhB1);
                        mma_bf16(acc[1][m], ah[m][g], blB0, blB1);
                    }
                }

                #pragma unroll
                for (int m = 0; m < 2; m++) {
                    float* r0 = Cw + (size_t)(m * 16 + grp) * CD + p * 16;
                    __stcs(reinterpret_cast<float4*>(r0),
                           make_float4(acc[0][m][0], acc[0][m][1],
                                       acc[1][m][0], acc[1][m][1]));
                    __stcs(reinterpret_cast<float4*>(r0 + (size_t)8 * CD),
                           make_float4(acc[0][m][2], acc[0][m][3],
                                       acc[1][m][2], acc[1][m][3]));
                }
            }
        } else {
            // =================== m unit (aliases A smem; after all C units) ===
            const int mt = u - NU_C;
            const int bt0 = mt * MTB;

            __syncthreads();
            if (cur_stripe != -2) {       // first m unit: load mu
                for (int i = tid; i < NS * NC; i += THREADS) mu_s[i] = mu[i];
                cur_stripe = -2;
            }
            {
                const float* ap = alpha + (size_t)bt0 * NS;
                for (int i = tid; i < MTB * NS; i += THREADS) {
                    const int j = i % NS;
                    a_s[i] = ap[i] * scs[j];
                }
            }
            __syncthreads();
            if (mact) {
                float mur[NS];
                #pragma unroll
                for (int j = 0; j < NS; j++) mur[j] = mu_s[j * NC + mc];
                #pragma unroll 4
                for (int rr = 0; rr < 64; rr++) {
                    const int r = mh * 64 + rr;
                    float s = 0.f;
                    #pragma unroll
                    for (int j = 0; j < NS; j++) s = fmaf(a_s[r * NS + j], mur[j], s);
                    __stcs(&m_out[(size_t)(bt0 + r) * NC + mc], s);
                }
            }
        }
    }
}

extern "C" void kernel_launch(void* const* d_in, const int* in_sizes, int n_in,
                              void* d_out, int out_size)
{
    const float* alpha = (const float*)d_in[0];   // [64,400,25]
    const float* mu    = (const float*)d_in[1];   // [25,80]
    const float* D     = (const float*)d_in[2];   // [25,80,80]
    const float* asc   = (const float*)d_in[3];   // [25]

    float* out = (float*)d_out;
    float* m_o = out;                 // [64,400,80]
    float* c_o = out + (BT * NC);     // [64,400,80,80]

    static int inited = 0;
    if (!inited) {
        cudaFuncSetAttribute(fused_kernel,
                             cudaFuncAttributeMaxDynamicSharedMemorySize, SMB);
        inited = 1;
    }

    fused_kernel<<<NBLK, THREADS, SMB>>>(alpha, mu, D, asc, m_o, c_o);
}